// round 17
// baseline (speedup 1.0000x reference)
#include <cuda_runtime.h>

#define EPS 1e-5f

typedef unsigned long long u64;

// ---------------- f32x2 helpers ----------------
__device__ __forceinline__ void fma2(u64& d, u64 a, u64 b) {
    asm volatile("fma.rn.f32x2 %0, %1, %2, %0;" : "+l"(d) : "l"(a), "l"(b));
}
__device__ __forceinline__ u64 dup2(float x) {
    u64 r; asm("mov.b64 %0, {%1, %1};" : "=l"(r) : "f"(x)); return r;
}
__device__ __forceinline__ float2 unpack2(u64 v) {
    float2 r; asm("mov.b64 {%0, %1}, %2;" : "=f"(r.x), "=f"(r.y) : "l"(v)); return r;
}

// ---------------- tf32 mma helpers ----------------
__device__ __forceinline__ float cvt_tf32(float x) {
    unsigned r; asm("cvt.rna.tf32.f32 %0, %1;" : "=r"(r) : "f"(x));
    return __uint_as_float(r);
}
__device__ __forceinline__ void mma_tf32(float* d, const unsigned* a, const unsigned* b) {
    asm volatile(
        "mma.sync.aligned.m16n8k8.row.col.f32.tf32.tf32.f32 "
        "{%0,%1,%2,%3}, {%4,%5,%6,%7}, {%8,%9}, {%0,%1,%2,%3};\n"
        : "+f"(d[0]), "+f"(d[1]), "+f"(d[2]), "+f"(d[3])
        : "r"(a[0]), "r"(a[1]), "r"(a[2]), "r"(a[3]), "r"(b[0]), "r"(b[1]));
}

// ---------------- scratch (device globals; no allocation allowed) ----------------
__device__ float g_invn[16384];               // 1/||x|| per position
__device__ float g_xnt[16384 * 144];          // normalized input, position-major [pos][c]
__device__ float g_wint[144 * 64];            // w_in transposed [c][o]
__device__ float g_w1oc[9 * 64 * 64];         // w1 as [drds][o][o2]
__device__ float g_w2jt[576 * 64];            // w2 as [j = rs*64+o2][o3]
__device__ float g_sin[64], g_tin[64];
__device__ float g_s1[64],  g_t1[64];
__device__ float g_s2[64],  g_t2[64];
__device__ float g_sout[144], g_tout[144];
__device__ float g_A[16384 * 25 * 64];        // post GEMM1+BN+ReLU  [pos][k][o]
__device__ float g_A1[16384 * 9 * 64];        // post conv1+BN+ReLU  [pos][rs][o2]
__device__ float g_B2[16384 * 64];            // post conv2+BN+ReLU  [pos][o3]

// ---------------- weight transpose + BN folding ----------------
__global__ void prep_kernel(const float* __restrict__ w_in,
                            const float* __restrict__ gin, const float* __restrict__ bin,
                            const float* __restrict__ min_, const float* __restrict__ vin,
                            const float* __restrict__ w1,
                            const float* __restrict__ g1, const float* __restrict__ b1,
                            const float* __restrict__ m1, const float* __restrict__ v1,
                            const float* __restrict__ w2,
                            const float* __restrict__ g2, const float* __restrict__ b2,
                            const float* __restrict__ m2, const float* __restrict__ v2,
                            const float* __restrict__ go, const float* __restrict__ bo,
                            const float* __restrict__ mo, const float* __restrict__ vo)
{
    int i = blockIdx.x * blockDim.x + threadIdx.x;   // grid covers 36864
    if (i < 36864) {
        // w1oc[drds][o][c] = w1[c][o][drds]   (c = output channel)
        int drds = i >> 12; int r1 = i & 4095;
        int o = r1 >> 6; int c = r1 & 63;
        g_w1oc[i] = w1[(c * 64 + o) * 9 + drds];
        // w2jt[j][o3] = w2[o3][o2][rs],  j = rs*64+o2
        int j = i >> 6; int o3 = i & 63;
        int rs = j >> 6; int o2 = j & 63;
        g_w2jt[i] = w2[(o3 * 64 + o2) * 9 + rs];
    }
    if (i < 9216) { int c = i >> 6; int o = i & 63; g_wint[i] = w_in[o * 144 + c]; }
    if (i < 64) {
        float s;
        s = gin[i] * rsqrtf(vin[i] + EPS); g_sin[i] = s; g_tin[i] = bin[i] - min_[i] * s;
        s = g1[i]  * rsqrtf(v1[i]  + EPS); g_s1[i]  = s; g_t1[i]  = b1[i]  - m1[i]  * s;
        s = g2[i]  * rsqrtf(v2[i]  + EPS); g_s2[i]  = s; g_t2[i]  = b2[i]  - m2[i]  * s;
    }
    if (i < 144) {
        float s = go[i] * rsqrtf(vo[i] + EPS); g_sout[i] = s; g_tout[i] = bo[i] - mo[i] * s;
    }
}

// ---------------- inverse L2 norm per position ----------------
__global__ void invn_kernel(const float* __restrict__ x)
{
    int p = blockIdx.x * 256 + threadIdx.x;          // 16384 positions
    int b = p >> 12, hw = p & 4095;
    const float* xb = x + (size_t)b * 589824 + hw;   // 144*4096
    float ss = 0.f;
    #pragma unroll 4
    for (int c = 0; c < 144; c++) { float v = xb[c * 4096]; ss += v * v; }
    g_invn[p] = 1.0f / fmaxf(sqrtf(ss), 1e-12f);
}

// ---------------- transpose + normalize: g_xnt[pos][c] = x[c][pos] * invn[pos] ----------------
__global__ void xpose_kernel(const float* __restrict__ x)
{
    __shared__ float tile[32][33];
    int p0 = blockIdx.x << 5;
    int c0 = blockIdx.y << 5;
    int tx = threadIdx.x, ty = threadIdx.y;          // 32 x 8
    int b = p0 >> 12, hw0 = p0 & 4095;
    float inv = g_invn[p0 + tx];
    const float* xb = x + (size_t)b * 589824 + hw0 + tx;
    #pragma unroll
    for (int i = 0; i < 4; i++) {
        int c = c0 + ty + (i << 3);
        if (c < 144) tile[ty + (i << 3)][tx] = xb[c << 12] * inv;
    }
    __syncthreads();
    #pragma unroll
    for (int i = 0; i < 4; i++) {
        int p = p0 + ty + (i << 3);
        int c = c0 + tx;
        if (c < 144) g_xnt[p * 144 + c] = tile[tx][ty + (i << 3)];
    }
}

// ---------------- GEMM1 as tf32 mma (mirror-symmetric, k=12..24 only) ----------------
// rows R = pos_local*13 + kt (104 valid, padded to 112), K=144 (2 chunks of 72), N=64.
// Row descriptors (mirror q position, self position) precomputed once in smem;
// staging loops are pure-shift indexed (112x16 + 112x2 float4).
__global__ void __launch_bounds__(256) gemm1_kernel()
{
    extern __shared__ float sm[];
    float* As = sm;                                  // 112*76 = 8512
    float* Bs = sm + 8512;                           // 72*72  = 5184
    int* rowq = (int*)(sm + 13696);                  // 112
    int* rowp = (int*)(sm + 13808);                  // 112
    int pos0 = blockIdx.x << 3;                      // 8 positions
    int tid = threadIdx.x;
    int lane = tid & 31, w = tid >> 5;
    int g = lane >> 2, t = lane & 3;
    int n0 = w << 3;

    // row descriptors, once
    if (tid < 112) {
        int r = tid;
        int pl = r / 13, kt = r - pl * 13;
        int p = pos0 + ((pl < 8) ? pl : 0);
        int k = kt + 12;
        int kh = k / 5, kw = k - kh * 5;
        int hh = (p >> 6) & 63, ww = p & 63;
        int qh = hh + kh - 2, qw = ww + kw - 2;
        bool ok = (r < 104) && ((unsigned)qh < 64u) && ((unsigned)qw < 64u);
        rowq[r] = ok ? ((p & ~4095) + (qh << 6) + qw) : -1;
        rowp[r] = p;
    }

    float acc[7][4];
    #pragma unroll
    for (int i = 0; i < 7; i++) {
        acc[i][0] = 0.f; acc[i][1] = 0.f; acc[i][2] = 0.f; acc[i][3] = 0.f;
    }

    for (int kc = 0; kc < 2; kc++) {
        __syncthreads();
        // main: 112 rows x 16 float4  (c offsets 0..63 of chunk)
        #pragma unroll
        for (int j2 = 0; j2 < 7; j2++) {
            int idx = tid + (j2 << 8);               // < 1792
            int r = idx >> 4, cf = idx & 15;
            int q = rowq[r];
            float4 v = make_float4(0.f, 0.f, 0.f, 0.f);
            if (q >= 0) {
                int c = kc * 72 + (cf << 2);
                float4 pa = *(const float4*)&g_xnt[q * 144 + c];
                float4 ce = *(const float4*)&g_xnt[rowp[r] * 144 + c];
                v.x = cvt_tf32(pa.x * ce.x);
                v.y = cvt_tf32(pa.y * ce.y);
                v.z = cvt_tf32(pa.z * ce.z);
                v.w = cvt_tf32(pa.w * ce.w);
            }
            *(float4*)&As[r * 76 + (cf << 2)] = v;
        }
        // tail: 112 rows x 2 float4  (c offsets 64..71 of chunk)
        if (tid < 224) {
            int r = tid >> 1, cf2 = tid & 1;
            int q = rowq[r];
            float4 v = make_float4(0.f, 0.f, 0.f, 0.f);
            if (q >= 0) {
                int c = kc * 72 + 64 + (cf2 << 2);
                float4 pa = *(const float4*)&g_xnt[q * 144 + c];
                float4 ce = *(const float4*)&g_xnt[rowp[r] * 144 + c];
                v.x = cvt_tf32(pa.x * ce.x);
                v.y = cvt_tf32(pa.y * ce.y);
                v.z = cvt_tf32(pa.z * ce.z);
                v.w = cvt_tf32(pa.w * ce.w);
            }
            *(float4*)&As[r * 76 + 64 + (cf2 << 2)] = v;
        }
        // stage Bs[c_local][o] from g_wint[c][o]
        #pragma unroll
        for (int j2 = 0; j2 < 5; j2++) {
            int idx = tid + (j2 << 8);
            if (idx < 1152) {
                int cl = idx >> 4, of = idx & 15;
                float4 v = *(const float4*)&g_wint[((kc * 72 + cl) << 6) + (of << 2)];
                v.x = cvt_tf32(v.x); v.y = cvt_tf32(v.y);
                v.z = cvt_tf32(v.z); v.w = cvt_tf32(v.w);
                *(float4*)&Bs[cl * 72 + (of << 2)] = v;
            }
        }
        __syncthreads();

        #pragma unroll
        for (int kk = 0; kk < 9; kk++) {
            int ko = kk << 3;
            unsigned b2[2];
            b2[0] = __float_as_uint(Bs[(ko + t) * 72 + n0 + g]);
            b2[1] = __float_as_uint(Bs[(ko + t + 4) * 72 + n0 + g]);
            #pragma unroll
            for (int i = 0; i < 7; i++) {
                unsigned a[4];
                const float* ar = As + ((i << 4) + g) * 76 + ko + t;
                a[0] = __float_as_uint(ar[0]);
                a[1] = __float_as_uint(ar[8 * 76]);
                a[2] = __float_as_uint(ar[4]);
                a[3] = __float_as_uint(ar[8 * 76 + 4]);
                mma_tf32(acc[i], a, b2);
            }
        }
    }

    // epilogue: BN+ReLU; write self slot + mirror partner + OOB constant
    int col = n0 + (t << 1);
    float2 s2 = *(const float2*)&g_sin[col];
    float2 tb = *(const float2*)&g_tin[col];
    float2 cst = make_float2(fmaxf(tb.x, 0.f), fmaxf(tb.y, 0.f));

    #pragma unroll
    for (int i = 0; i < 7; i++) {
        #pragma unroll
        for (int e = 0; e < 2; e++) {
            int r = (i << 4) + g + (e << 3);
            if (r < 104) {
                int pl = r / 13, kt = r - pl * 13;
                int p = pos0 + pl;
                int k = kt + 12;
                float2 rv;
                rv.x = fmaxf(acc[i][(e << 1) + 0] * s2.x + tb.x, 0.f);
                rv.y = fmaxf(acc[i][(e << 1) + 1] * s2.y + tb.y, 0.f);
                *(float2*)&g_A[(((size_t)p * 25 + k) << 6) + col] = rv;
                if (k != 12) {
                    int kh = k / 5, kw = k - kh * 5;
                    int dh = kh - 2, dw = kw - 2;
                    int mk = 24 - k;
                    int hh = (p >> 6) & 63, ww = p & 63;
                    int qh = hh + dh, qw = ww + dw;
                    if ((unsigned)qh < 64u && (unsigned)qw < 64u) {
                        int q = (p & ~4095) + (qh << 6) + qw;
                        *(float2*)&g_A[(((size_t)q * 25 + mk) << 6) + col] = rv;
                    }
                    int rh = hh - dh, rw = ww - dw;
                    if (!((unsigned)rh < 64u && (unsigned)rw < 64u)) {
                        *(float2*)&g_A[(((size_t)p * 25 + mk) << 6) + col] = cst;
                    }
                }
            }
        }
    }
}

// ---------------- Conv1 as tf32 tensor-core GEMM ----------------
// Staging row maps hoisted out of the drds loop (division-free inner staging).
__global__ void __launch_bounds__(256) conv1_kernel()
{
    extern __shared__ float sm[];
    float* As = sm;                                  // 128*68 = 8704
    float* ws = sm + 8704;                           // 64*72  = 4608
    int r0 = blockIdx.x << 7;
    int tid = threadIdx.x;
    int lane = tid & 31, w = tid >> 5;
    int g = lane >> 2, t = lane & 3;
    int m0 = (w >> 1) << 5;                          // 0,32,64,96
    int n0 = (w & 1) << 5;                           // 0,32

    // precompute staging addresses (drds-invariant)
    int srcA[8], dstA[8];
    #pragma unroll
    for (int j2 = 0; j2 < 8; j2++) {
        int idx = tid + (j2 << 8);                   // 2048 float4
        int row = idx >> 4, cf = idx & 15;
        int R = r0 + row;
        int p = R / 9, rs = R - p * 9;
        srcA[j2] = p * 1600 + ((rs + 2 * (rs / 3)) << 6) + (cf << 2);
        dstA[j2] = row * 68 + (cf << 2);
    }
    int srcB[4], dstB[4];
    #pragma unroll
    for (int j2 = 0; j2 < 4; j2++) {
        int idx = tid + (j2 << 8);                   // 1024 float4
        int row = idx >> 4, cf = idx & 15;
        srcB[j2] = (row << 6) + (cf << 2);
        dstB[j2] = row * 72 + (cf << 2);
    }

    float acc[2][4][4];
    #pragma unroll
    for (int i = 0; i < 2; i++)
        #pragma unroll
        for (int j = 0; j < 4; j++) {
            acc[i][j][0] = 0.f; acc[i][j][1] = 0.f;
            acc[i][j][2] = 0.f; acc[i][j][3] = 0.f;
        }

    for (int drds = 0; drds < 9; drds++) {
        int dr = drds / 3, ds = drds - dr * 3;
        int shoff = (dr * 5 + ds) << 6;
        __syncthreads();
        #pragma unroll
        for (int j2 = 0; j2 < 8; j2++) {
            float4 v = *(const float4*)(g_A + (size_t)srcA[j2] + shoff);
            float4 o;
            o.x = cvt_tf32(v.x); o.y = cvt_tf32(v.y);
            o.z = cvt_tf32(v.z); o.w = cvt_tf32(v.w);
            *(float4*)(As + dstA[j2]) = o;
        }
        #pragma unroll
        for (int j2 = 0; j2 < 4; j2++) {
            float4 v = *(const float4*)(g_w1oc + (drds << 12) + srcB[j2]);
            float4 o;
            o.x = cvt_tf32(v.x); o.y = cvt_tf32(v.y);
            o.z = cvt_tf32(v.z); o.w = cvt_tf32(v.w);
            *(float4*)(ws + dstB[j2]) = o;
        }
        __syncthreads();

        #pragma unroll
        for (int kk = 0; kk < 8; kk++) {
            int ko = kk << 3;
            unsigned a[2][4], b[4][2];
            #pragma unroll
            for (int i = 0; i < 2; i++) {
                const float* ar = As + (m0 + (i << 4) + g) * 68 + ko + t;
                a[i][0] = __float_as_uint(ar[0]);
                a[i][1] = __float_as_uint(ar[8 * 68]);
                a[i][2] = __float_as_uint(ar[4]);
                a[i][3] = __float_as_uint(ar[8 * 68 + 4]);
            }
            #pragma unroll
            for (int j = 0; j < 4; j++) {
                const float* br = ws + (ko + t) * 72 + n0 + (j << 3) + g;
                b[j][0] = __float_as_uint(br[0]);
                b[j][1] = __float_as_uint(br[4 * 72]);
            }
            #pragma unroll
            for (int i = 0; i < 2; i++)
                #pragma unroll
                for (int j = 0; j < 4; j++)
                    mma_tf32(acc[i][j], a[i], b[j]);
        }
    }

    #pragma unroll
    for (int i = 0; i < 2; i++) {
        size_t R = (size_t)r0 + m0 + (i << 4) + g;
        #pragma unroll
        for (int j = 0; j < 4; j++) {
            int col = n0 + (j << 3) + (t << 1);
            float2 s = *(const float2*)&g_s1[col];
            float2 tb = *(const float2*)&g_t1[col];
            float2 o0, o1;
            o0.x = fmaxf(acc[i][j][0] * s.x + tb.x, 0.f);
            o0.y = fmaxf(acc[i][j][1] * s.y + tb.y, 0.f);
            o1.x = fmaxf(acc[i][j][2] * s.x + tb.x, 0.f);
            o1.y = fmaxf(acc[i][j][3] * s.y + tb.y, 0.f);
            *(float2*)&g_A1[(R << 6) + col]       = o0;
            *(float2*)&g_A1[((R + 8) << 6) + col] = o1;
        }
    }
}

// ---------------- Conv2 as tf32 mma: M=16384, K=576 (9 chunks), N=64 ----------------
__global__ void __launch_bounds__(256) conv2_kernel()
{
    extern __shared__ float sm[];
    float* As = sm;                                  // 64*68 = 4352
    float* Bs = sm + 4352;                           // 64*72 = 4608
    int pos0 = blockIdx.x << 6;
    int tid = threadIdx.x;
    int lane = tid & 31, w = tid >> 5;
    int g = lane >> 2, t = lane & 3;
    int m0 = (w >> 1) << 4;                          // 0,16,32,48
    int n0 = (w & 1) << 5;                           // 0,32

    float acc[4][4];
    #pragma unroll
    for (int j = 0; j < 4; j++) {
        acc[j][0] = 0.f; acc[j][1] = 0.f; acc[j][2] = 0.f; acc[j][3] = 0.f;
    }

    for (int jc = 0; jc < 9; jc++) {
        __syncthreads();
        #pragma unroll
        for (int j2 = 0; j2 < 4; j2++) {
            int idx = tid + (j2 << 8);               // 1024 float4
            int row = idx >> 4, cf = idx & 15;
            float4 v = *(const float4*)&g_A1[(size_t)(pos0 + row) * 576 + (jc << 6) + (cf << 2)];
            float4 o;
            o.x = cvt_tf32(v.x); o.y = cvt_tf32(v.y);
            o.z = cvt_tf32(v.z); o.w = cvt_tf32(v.w);
            *(float4*)(As + row * 68 + (cf << 2)) = o;
        }
        #pragma unroll
        for (int j2 = 0; j2 < 4; j2++) {
            int idx = tid + (j2 << 8);               // 1024 float4
            int row = idx >> 4, cf = idx & 15;
            float4 v = *(const float4*)&g_w2jt[((jc << 6) + row) * 64 + (cf << 2)];
            float4 o;
            o.x = cvt_tf32(v.x); o.y = cvt_tf32(v.y);
            o.z = cvt_tf32(v.z); o.w = cvt_tf32(v.w);
            *(float4*)(Bs + row * 72 + (cf << 2)) = o;
        }
        __syncthreads();

        #pragma unroll
        for (int kk = 0; kk < 8; kk++) {
            int ko = kk << 3;
            unsigned a[4];
            const float* ar = As + (m0 + g) * 68 + ko + t;
            a[0] = __float_as_uint(ar[0]);
            a[1] = __float_as_uint(ar[8 * 68]);
            a[2] = __float_as_uint(ar[4]);
            a[3] = __float_as_uint(ar[8 * 68 + 4]);
            #pragma unroll
            for (int j = 0; j < 4; j++) {
                unsigned b[2];
                const float* br = Bs + (ko + t) * 72 + n0 + (j << 3) + g;
                b[0] = __float_as_uint(br[0]);
                b[1] = __float_as_uint(br[4 * 72]);
                mma_tf32(acc[j], a, b);
            }
        }
    }

    size_t R = (size_t)pos0 + m0 + g;
    #pragma unroll
    for (int j = 0; j < 4; j++) {
        int col = n0 + (j << 3) + (t << 1);
        float2 s = *(const float2*)&g_s2[col];
        float2 tb = *(const float2*)&g_t2[col];
        float2 o0, o1;
        o0.x = fmaxf(acc[j][0] * s.x + tb.x, 0.f);
        o0.y = fmaxf(acc[j][1] * s.y + tb.y, 0.f);
        o1.x = fmaxf(acc[j][2] * s.x + tb.x, 0.f);
        o1.y = fmaxf(acc[j][3] * s.y + tb.y, 0.f);
        *(float2*)&g_B2[(R << 6) + col]       = o0;
        *(float2*)&g_B2[((R + 8) << 6) + col] = o1;
    }
}

// ---------------- GEMM out: 64->144, BN (no ReLU) ----------------
__global__ void __launch_bounds__(256) gemmout_kernel(const float* __restrict__ w_out,
                                                      float* __restrict__ out)
{
    extern __shared__ float sm[];                    // 4160 + 9216 floats
    float* B2t = sm;
    float* ws  = sm + 4160;
    int pos0 = blockIdx.x << 6;
    int tid = threadIdx.x;

    for (int idx = tid; idx < 4096; idx += 256) {
        int p = idx >> 6, cm = idx & 63;
        B2t[cm * 65 + p] = g_B2[(pos0 << 6) + idx];
    }
    for (int idx = tid; idx < 9216; idx += 256) {
        int oc = idx >> 6, cm = idx & 63;
        ws[cm * 144 + oc] = w_out[idx];              // w_out[oc][cm]
    }
    __syncthreads();

    int pl = tid & 63, ocg = tid >> 6;               // ocg block of 36 oc
    u64 acc[18];
    #pragma unroll
    for (int j = 0; j < 18; j++) acc[j] = 0;

    for (int cm = 0; cm < 64; cm++) {
        u64 bv = dup2(B2t[cm * 65 + pl]);
        const ulonglong2* wp = (const ulonglong2*)&ws[cm * 144 + ocg * 36];
        #pragma unroll
        for (int j = 0; j < 9; j++) {
            ulonglong2 w = wp[j];
            fma2(acc[2 * j],     w.x, bv);
            fma2(acc[2 * j + 1], w.y, bv);
        }
    }

    int b = pos0 >> 12, hw0 = pos0 & 4095;
    float* op = out + (size_t)b * 589824 + hw0 + pl;
    #pragma unroll
    for (int j = 0; j < 18; j++) {
        int oc0 = ocg * 36 + 2 * j;
        float2 v = unpack2(acc[j]);
        op[(size_t)oc0 * 4096]       = v.x * g_sout[oc0]     + g_tout[oc0];
        op[(size_t)(oc0 + 1) * 4096] = v.y * g_sout[oc0 + 1] + g_tout[oc0 + 1];
    }
}

// ---------------- launch ----------------
extern "C" void kernel_launch(void* const* d_in, const int* in_sizes, int n_in,
                              void* d_out, int out_size)
{
    (void)in_sizes; (void)n_in; (void)out_size;
    const float* x     = (const float*)d_in[0];
    const float* w_in  = (const float*)d_in[1];
    const float* gin   = (const float*)d_in[2];
    const float* bin   = (const float*)d_in[3];
    const float* min_  = (const float*)d_in[4];
    const float* vin   = (const float*)d_in[5];
    const float* w1    = (const float*)d_in[6];
    const float* g1    = (const float*)d_in[7];
    const float* b1    = (const float*)d_in[8];
    const float* m1    = (const float*)d_in[9];
    const float* v1    = (const float*)d_in[10];
    const float* w2    = (const float*)d_in[11];
    const float* g2    = (const float*)d_in[12];
    const float* b2    = (const float*)d_in[13];
    const float* m2    = (const float*)d_in[14];
    const float* v2    = (const float*)d_in[15];
    const float* w_out = (const float*)d_in[16];
    const float* go    = (const float*)d_in[17];
    const float* bo    = (const float*)d_in[18];
    const float* mo    = (const float*)d_in[19];
    const float* vo    = (const float*)d_in[20];
    float* out = (float*)d_out;

    cudaFuncSetAttribute(gemm1_kernel,   cudaFuncAttributeMaxDynamicSharedMemorySize, 55680);
    cudaFuncSetAttribute(conv1_kernel,   cudaFuncAttributeMaxDynamicSharedMemorySize, 53248);
    cudaFuncSetAttribute(conv2_kernel,   cudaFuncAttributeMaxDynamicSharedMemorySize, 35840);
    cudaFuncSetAttribute(gemmout_kernel, cudaFuncAttributeMaxDynamicSharedMemorySize, 53504);

    prep_kernel<<<144, 256>>>(w_in, gin, bin, min_, vin,
                              w1, g1, b1, m1, v1,
                              w2, g2, b2, m2, v2,
                              go, bo, mo, vo);
    invn_kernel<<<64, 256>>>(x);
    xpose_kernel<<<dim3(512, 5), dim3(32, 8)>>>(x);
    gemm1_kernel<<<2048, 256, 55680>>>();
    conv1_kernel<<<1152, 256, 53248>>>();
    conv2_kernel<<<256, 256, 35840>>>();
    gemmout_kernel<<<256, 256, 53504>>>(w_out, out);
}